// round 13
// baseline (speedup 1.0000x reference)
#include <cuda_runtime.h>
#include <math.h>

#define N_CLUSTS 50000

// Static device scratch (allowed; cudaMalloc is not)
__device__ float4 g_acc[N_CLUSTS * 3];   // [sx,sy,sz,cnt] [sxx,sxy,sxz,syy] [syz,szz,-,-]
__device__ float  g_sc[N_CLUSTS];        // sum x0*np0

// One 32B record per cluster: {cx,cy,cz,dirwt, v0x,v0y,v0z,multi}
struct __align__(32) CV {
    float4 ct;
    float4 vv;
};
__device__ CV g_cv[N_CLUSTS];

// Vectorized global reductions (ptxas-validated: .v2/.v4 only, 128-bit max).
__device__ __forceinline__ void red_add_v4(float4* addr, float a, float b, float c, float d) {
    asm volatile("red.global.add.v4.f32 [%0], {%1,%2,%3,%4};"
                 :: "l"(addr), "f"(a), "f"(b), "f"(c), "f"(d) : "memory");
}
__device__ __forceinline__ void red_add_v2(float4* addr, float a, float b) {
    asm volatile("red.global.add.v2.f32 [%0], {%1,%2};"
                 :: "l"(addr), "f"(a), "f"(b) : "memory");
}

// 256-bit read-only gather (sm_100a) — validated in rounds 6/9/11/12.
__device__ __forceinline__ void ldg_v8(const CV* p, float r[8]) {
    asm("ld.global.nc.v8.f32 {%0,%1,%2,%3,%4,%5,%6,%7}, [%8];"
        : "=f"(r[0]), "=f"(r[1]), "=f"(r[2]), "=f"(r[3]),
          "=f"(r[4]), "=f"(r[5]), "=f"(r[6]), "=f"(r[7])
        : "l"(p));
}

// ---------------------------------------------------------------------------
// Pass 1: count + raw moments. 2 loads + 3 vector reds per voxel (floor).
__global__ void __launch_bounds__(256) k_accum(const float* __restrict__ data,
                                               const int* __restrict__ cid, int n) {
    int i = blockIdx.x * blockDim.x + threadIdx.x;
    if (i >= n) return;
    int c = __ldg(cid + i);
    const float* p = data + (size_t)i * 6;
    float  x  = __ldg(p + 1);
    float2 yz = __ldg((const float2*)(p + 2));   // 8B-aligned: 6i+2 even
    float  y = yz.x, z = yz.y;
    float4* acc = &g_acc[c * 3];
    red_add_v4(acc,     x,     y,     z,     1.0f);
    red_add_v4(acc + 1, x * x, x * y, x * z, y * y);
    red_add_v2(acc + 2, y * z, z * z);
}

// ---------------------------------------------------------------------------
// Per-cluster (one thread each): center, covariance, Jacobi eigensolve, B, dirwt.
__global__ void k_eig(float* __restrict__ out) {
    int c = blockIdx.x * blockDim.x + threadIdx.x;
    if (c >= N_CLUSTS) return;

    float4 s0 = g_acc[c * 3 + 0];
    float4 s1 = g_acc[c * 3 + 1];
    float4 s2 = g_acc[c * 3 + 2];
    float cnt = s0.w;
    float inv = 1.f / fmaxf(cnt, 1.f);
    float cx = s0.x * inv, cy = s0.y * inv, cz = s0.z * inv;

    // A = Sum(x x^T) - cnt * c c^T
    float a00 = s1.x - cnt * cx * cx;
    float a01 = s1.y - cnt * cx * cy;
    float a02 = s1.z - cnt * cx * cz;
    float a11 = s1.w - cnt * cy * cy;
    float a12 = s2.x - cnt * cy * cz;
    float a22 = s2.y - cnt * cz * cz;

    // --- cyclic Jacobi, 6 sweeps (quadratic convergence; ample margin) ---
    float A[3][3] = {{a00, a01, a02}, {a01, a11, a12}, {a02, a12, a22}};
    float V[3][3] = {{1.f, 0.f, 0.f}, {0.f, 1.f, 0.f}, {0.f, 0.f, 1.f}};
    const int Pp[3] = {0, 0, 1};
    const int Qq[3] = {1, 2, 2};
    #pragma unroll 1
    for (int sweep = 0; sweep < 6; sweep++) {
        #pragma unroll
        for (int r = 0; r < 3; r++) {
            int p = Pp[r], q = Qq[r];
            float apq = A[p][q];
            if (fabsf(apq) > 0.f) {
                float tau = (A[q][q] - A[p][p]) / (2.f * apq);
                float t = copysignf(1.f / (fabsf(tau) + sqrtf(1.f + tau * tau)), tau);
                float cth = rsqrtf(1.f + t * t);
                float sth = t * cth;
                #pragma unroll
                for (int k = 0; k < 3; k++) {
                    float akp = A[k][p], akq = A[k][q];
                    A[k][p] = cth * akp - sth * akq;
                    A[k][q] = sth * akp + cth * akq;
                }
                #pragma unroll
                for (int k = 0; k < 3; k++) {
                    float apk = A[p][k], aqk = A[q][k];
                    A[p][k] = cth * apk - sth * aqk;
                    A[q][k] = sth * apk + cth * aqk;
                }
                #pragma unroll
                for (int k = 0; k < 3; k++) {
                    float vkp = V[k][p], vkq = V[k][q];
                    V[k][p] = cth * vkp - sth * vkq;
                    V[k][q] = sth * vkp + cth * vkq;
                }
            }
        }
    }

    float w0 = A[0][0], w1 = A[1][1], w2 = A[2][2];
    int i2 = (w1 > w0) ? 1 : 0;
    float wt = (w1 > w0) ? w1 : w0;
    if (w2 > wt) { i2 = 2; wt = w2; }
    float wa, wb;
    if (i2 == 0)      { wa = w1; wb = w2; }
    else if (i2 == 1) { wa = w0; wb = w2; }
    else              { wa = w0; wb = w1; }
    float wmid = fmaxf(wa, wb);

    float safe = (wt > 0.f) ? wt : 1.f;
    float dirwt = 1.f - wmid / safe;
    bool multi = (cnt >= 2.f);
    float bm = multi ? (1.f / safe) : 0.f;

    float v0x = V[0][i2], v0y = V[1][i2], v0z = V[2][i2];

    // Vectorized 16B-aligned stores for feats [center | B] (out rows are 64B).
    float4* o4 = (float4*)(out + (size_t)c * 16);
    o4[0] = make_float4(cx, cy, cz, a00 * bm);
    o4[1] = make_float4(a01 * bm, a02 * bm, a01 * bm, a11 * bm);
    o4[2] = make_float4(a12 * bm, a02 * bm, a12 * bm, a22 * bm);
    out[(size_t)c * 16 + 15] = cnt;

    CV cv;
    cv.ct = make_float4(cx, cy, cz, dirwt);
    cv.vv = make_float4(v0x, v0y, v0z, multi ? 1.f : 0.f);
    g_cv[c] = cv;
}

// ---------------------------------------------------------------------------
// Pass 2: sc = segment_sum(x0 * ||x - c - x0*v0||).
// One voxel per thread (A/B-validated best), single 32B record gather.
__global__ void __launch_bounds__(256) k_sc(const float* __restrict__ data,
                                            const int* __restrict__ cid, int n) {
    int i = blockIdx.x * blockDim.x + threadIdx.x;
    if (i >= n) return;
    int c = __ldg(cid + i);
    const float* p = data + (size_t)i * 6;
    float  x  = __ldg(p + 1);
    float2 yz = __ldg((const float2*)(p + 2));
    float r[8];
    ldg_v8(&g_cv[c], r);   // {cx,cy,cz,dirwt, v0x,v0y,v0z,multi}
    float dx = x - r[0], dy = yz.x - r[1], dz = yz.y - r[2];
    float x0 = dx * r[4] + dy * r[5] + dz * r[6];
    float px = dx - x0 * r[4];
    float py = dy - x0 * r[5];
    float pz = dz - x0 * r[6];
    float np0 = sqrtf(px * px + py * py + pz * pz);
    atomicAdd(&g_sc[c], x0 * np0);
}

// ---------------------------------------------------------------------------
// Finalize v0: sign flip by sc, scale by dirwt, mask by multi.
__global__ void k_final(float* __restrict__ out) {
    int c = blockIdx.x * blockDim.x + threadIdx.x;
    if (c >= N_CLUSTS) return;
    float sc = g_sc[c];
    CV cv = g_cv[c];
    float s = (sc < 0.f) ? -1.f : 1.f;
    float f = s * cv.ct.w * cv.vv.w;   // sign * dirwt * multi
    float* o = out + (size_t)c * 16;
    o[12] = cv.vv.x * f;
    o[13] = cv.vv.y * f;
    o[14] = cv.vv.z * f;
}

// ---------------------------------------------------------------------------
extern "C" void kernel_launch(void* const* d_in, const int* in_sizes, int n_in,
                              void* d_out, int out_size) {
    const float* data = (const float*)d_in[0];
    const int*   cid  = (const int*)d_in[1];
    float* out = (float*)d_out;
    int n = in_sizes[1];   // number of voxels

    // Zero scratch via graph-capturable memset nodes (no alloc, async).
    void* p_acc = nullptr;
    void* p_sc  = nullptr;
    cudaGetSymbolAddress(&p_acc, g_acc);
    cudaGetSymbolAddress(&p_sc,  g_sc);
    cudaMemsetAsync(p_acc, 0, sizeof(float4) * N_CLUSTS * 3, 0);
    cudaMemsetAsync(p_sc,  0, sizeof(float)  * N_CLUSTS,     0);

    k_accum<<<(n + 255) / 256, 256>>>(data, cid, n);
    k_eig  <<<(N_CLUSTS + 127) / 128, 128>>>(out);
    k_sc   <<<(n + 255) / 256, 256>>>(data, cid, n);
    k_final<<<(N_CLUSTS + 255) / 256, 256>>>(out);
}

// round 15
// speedup vs baseline: 1.0315x; 1.0315x over previous
#include <cuda_runtime.h>
#include <math.h>

#define N_CLUSTS 50000

// Static device scratch (allowed; cudaMalloc is not)
__device__ float4 g_acc[N_CLUSTS * 3];   // [sx,sy,sz,cnt] [sxx,sxy,sxz,syy] [syz,szz,-,-]
__device__ float  g_sc[N_CLUSTS];        // sum x0*np0 (zeroed by k_eig)

// One 32B record per cluster: {cx,cy,cz,dirwt, v0x,v0y,v0z,cnt}
struct __align__(32) CV {
    float4 ct;   // cx, cy, cz, dirwt
    float4 vv;   // v0x, v0y, v0z, cnt
};
__device__ CV g_cv[N_CLUSTS];

// Vectorized global reductions (ptxas-validated: .v2/.v4 only, 128-bit max).
__device__ __forceinline__ void red_add_v4(float4* addr, float a, float b, float c, float d) {
    asm volatile("red.global.add.v4.f32 [%0], {%1,%2,%3,%4};"
                 :: "l"(addr), "f"(a), "f"(b), "f"(c), "f"(d) : "memory");
}
__device__ __forceinline__ void red_add_v2(float4* addr, float a, float b) {
    asm volatile("red.global.add.v2.f32 [%0], {%1,%2};"
                 :: "l"(addr), "f"(a), "f"(b) : "memory");
}

// 256-bit read-only gather (sm_100a) — validated in rounds 6/9/11/12.
__device__ __forceinline__ void ldg_v8(const CV* p, float r[8]) {
    asm("ld.global.nc.v8.f32 {%0,%1,%2,%3,%4,%5,%6,%7}, [%8];"
        : "=f"(r[0]), "=f"(r[1]), "=f"(r[2]), "=f"(r[3]),
          "=f"(r[4]), "=f"(r[5]), "=f"(r[6]), "=f"(r[7])
        : "l"(p));
}

// ---------------------------------------------------------------------------
// Pass 1: count + raw moments. 2 loads + 3 vector reds per voxel (floor).
__global__ void __launch_bounds__(256) k_accum(const float* __restrict__ data,
                                               const int* __restrict__ cid, int n) {
    int i = blockIdx.x * blockDim.x + threadIdx.x;
    if (i >= n) return;
    int c = __ldg(cid + i);
    const float* p = data + (size_t)i * 6;
    float  x  = __ldg(p + 1);
    float2 yz = __ldg((const float2*)(p + 2));   // 8B-aligned: 6i+2 even
    float  y = yz.x, z = yz.y;
    float4* acc = &g_acc[c * 3];
    red_add_v4(acc,     x,     y,     z,     1.0f);
    red_add_v4(acc + 1, x * x, x * y, x * z, y * y);
    red_add_v2(acc + 2, y * z, z * z);
}

// ---------------------------------------------------------------------------
// Per-cluster (one thread each): center, covariance, Jacobi eigensolve, B, dirwt.
// Also zeroes g_sc[c] for the following k_sc pass.
__global__ void k_eig(float* __restrict__ out) {
    int c = blockIdx.x * blockDim.x + threadIdx.x;
    if (c >= N_CLUSTS) return;

    g_sc[c] = 0.f;   // free store: replaces a memset node

    float4 s0 = g_acc[c * 3 + 0];
    float4 s1 = g_acc[c * 3 + 1];
    float4 s2 = g_acc[c * 3 + 2];
    float cnt = s0.w;
    float inv = 1.f / fmaxf(cnt, 1.f);
    float cx = s0.x * inv, cy = s0.y * inv, cz = s0.z * inv;

    // A = Sum(x x^T) - cnt * c c^T
    float a00 = s1.x - cnt * cx * cx;
    float a01 = s1.y - cnt * cx * cy;
    float a02 = s1.z - cnt * cx * cz;
    float a11 = s1.w - cnt * cy * cy;
    float a12 = s2.x - cnt * cy * cz;
    float a22 = s2.y - cnt * cz * cz;

    // --- cyclic Jacobi, 5 sweeps (converged: 8 vs 6 sweeps changed rel_err
    //     only in the 4th digit; 5 keeps quadratic-convergence margin) ---
    float A[3][3] = {{a00, a01, a02}, {a01, a11, a12}, {a02, a12, a22}};
    float V[3][3] = {{1.f, 0.f, 0.f}, {0.f, 1.f, 0.f}, {0.f, 0.f, 1.f}};
    const int Pp[3] = {0, 0, 1};
    const int Qq[3] = {1, 2, 2};
    #pragma unroll 1
    for (int sweep = 0; sweep < 5; sweep++) {
        #pragma unroll
        for (int r = 0; r < 3; r++) {
            int p = Pp[r], q = Qq[r];
            float apq = A[p][q];
            if (fabsf(apq) > 0.f) {
                float tau = (A[q][q] - A[p][p]) / (2.f * apq);
                float t = copysignf(1.f / (fabsf(tau) + sqrtf(1.f + tau * tau)), tau);
                float cth = rsqrtf(1.f + t * t);
                float sth = t * cth;
                #pragma unroll
                for (int k = 0; k < 3; k++) {
                    float akp = A[k][p], akq = A[k][q];
                    A[k][p] = cth * akp - sth * akq;
                    A[k][q] = sth * akp + cth * akq;
                }
                #pragma unroll
                for (int k = 0; k < 3; k++) {
                    float apk = A[p][k], aqk = A[q][k];
                    A[p][k] = cth * apk - sth * aqk;
                    A[q][k] = sth * apk + cth * aqk;
                }
                #pragma unroll
                for (int k = 0; k < 3; k++) {
                    float vkp = V[k][p], vkq = V[k][q];
                    V[k][p] = cth * vkp - sth * vkq;
                    V[k][q] = sth * vkp + cth * vkq;
                }
            }
        }
    }

    float w0 = A[0][0], w1 = A[1][1], w2 = A[2][2];
    int i2 = (w1 > w0) ? 1 : 0;
    float wt = (w1 > w0) ? w1 : w0;
    if (w2 > wt) { i2 = 2; wt = w2; }
    float wa, wb;
    if (i2 == 0)      { wa = w1; wb = w2; }
    else if (i2 == 1) { wa = w0; wb = w2; }
    else              { wa = w0; wb = w1; }
    float wmid = fmaxf(wa, wb);

    float safe = (wt > 0.f) ? wt : 1.f;
    float dirwt = 1.f - wmid / safe;
    bool multi = (cnt >= 2.f);
    float bm = multi ? (1.f / safe) : 0.f;

    float v0x = V[0][i2], v0y = V[1][i2], v0z = V[2][i2];

    // Vectorized 16B-aligned stores for feats [center | B]; o[12..15] written
    // entirely by k_final.
    float4* o4 = (float4*)(out + (size_t)c * 16);
    o4[0] = make_float4(cx, cy, cz, a00 * bm);
    o4[1] = make_float4(a01 * bm, a02 * bm, a01 * bm, a11 * bm);
    o4[2] = make_float4(a12 * bm, a02 * bm, a12 * bm, a22 * bm);

    CV cv;
    cv.ct = make_float4(cx, cy, cz, dirwt);
    cv.vv = make_float4(v0x, v0y, v0z, cnt);
    g_cv[c] = cv;
}

// ---------------------------------------------------------------------------
// Pass 2: sc = segment_sum(x0 * ||x - c - x0*v0||).
// One voxel per thread (A/B-validated best), single 32B record gather.
__global__ void __launch_bounds__(256) k_sc(const float* __restrict__ data,
                                            const int* __restrict__ cid, int n) {
    int i = blockIdx.x * blockDim.x + threadIdx.x;
    if (i >= n) return;
    int c = __ldg(cid + i);
    const float* p = data + (size_t)i * 6;
    float  x  = __ldg(p + 1);
    float2 yz = __ldg((const float2*)(p + 2));
    float r[8];
    ldg_v8(&g_cv[c], r);   // {cx,cy,cz,dirwt, v0x,v0y,v0z,cnt}
    float dx = x - r[0], dy = yz.x - r[1], dz = yz.y - r[2];
    float x0 = dx * r[4] + dy * r[5] + dz * r[6];
    float px = dx - x0 * r[4];
    float py = dy - x0 * r[5];
    float pz = dz - x0 * r[6];
    float np0 = sqrtf(px * px + py * py + pz * pz);
    atomicAdd(&g_sc[c], x0 * np0);
}

// ---------------------------------------------------------------------------
// Finalize: o[12..15] = {v0 * sign(sc) * dirwt * multi, cnt} as one STG.128.
__global__ void __launch_bounds__(256) k_final(float* __restrict__ out) {
    int c = blockIdx.x * blockDim.x + threadIdx.x;
    if (c >= N_CLUSTS) return;
    float sc = g_sc[c];
    CV cv = g_cv[c];
    float cnt = cv.vv.w;
    float s = (sc < 0.f) ? -1.f : 1.f;
    float f = s * cv.ct.w * ((cnt >= 2.f) ? 1.f : 0.f);   // sign * dirwt * multi
    float4* o4 = (float4*)(out + (size_t)c * 16);
    o4[3] = make_float4(cv.vv.x * f, cv.vv.y * f, cv.vv.z * f, cnt);
}

// ---------------------------------------------------------------------------
extern "C" void kernel_launch(void* const* d_in, const int* in_sizes, int n_in,
                              void* d_out, int out_size) {
    const float* data = (const float*)d_in[0];
    const int*   cid  = (const int*)d_in[1];
    float* out = (float*)d_out;
    int n = in_sizes[1];   // number of voxels

    // Zero the moment accumulators via a graph-capturable memset node.
    void* p_acc = nullptr;
    cudaGetSymbolAddress(&p_acc, g_acc);
    cudaMemsetAsync(p_acc, 0, sizeof(float4) * N_CLUSTS * 3, 0);

    k_accum<<<(n + 255) / 256, 256>>>(data, cid, n);
    k_eig  <<<(N_CLUSTS + 127) / 128, 128>>>(out);
    k_sc   <<<(n + 255) / 256, 256>>>(data, cid, n);
    k_final<<<(N_CLUSTS + 255) / 256, 256>>>(out);
}